// round 1
// baseline (speedup 1.0000x reference)
#include <cuda_runtime.h>
#include <cuda_bf16.h>

// Problem constants
#define F 26
#define B 16384
#define V 100000
#define D 32
#define H 13

// Scratch for the SE-net gate (scale) vector — device global, no allocation.
__device__ float g_scale[F];

// Kernel 1: compute scale[f] = sigmoid( w2 @ relu( w1 @ mean_d(emb[f, x[f,B-1], :]) ) )
// Only the LAST batch row feeds the gate (reference: scale = gate[-1]).
// One warp does everything.
__global__ void se_gate_kernel(const int* __restrict__ x,
                               const float* __restrict__ tables,
                               const float* __restrict__ w1,
                               const float* __restrict__ w2) {
    __shared__ float se_in[F];
    __shared__ float h[H];
    int t = threadIdx.x;

    if (t < F) {
        int idx = x[t * B + (B - 1)];
        const float4* row = reinterpret_cast<const float4*>(
            tables + (size_t)t * ((size_t)V * D) + (size_t)idx * D);
        float s = 0.f;
        #pragma unroll
        for (int i = 0; i < D / 4; i++) {
            float4 v = row[i];
            s += v.x + v.y + v.z + v.w;
        }
        se_in[t] = s * (1.0f / (float)D);
    }
    __syncwarp();

    if (t < H) {
        float acc = 0.f;
        #pragma unroll
        for (int f = 0; f < F; f++) acc += w1[t * F + f] * se_in[f];
        h[t] = fmaxf(acc, 0.f);
    }
    __syncwarp();

    if (t < F) {
        float acc = 0.f;
        #pragma unroll
        for (int j = 0; j < H; j++) acc += w2[t * H + j] * h[j];
        g_scale[t] = 1.0f / (1.0f + __expf(-acc));
    }
}

// Kernel 2: out[b, f*D+d] = tables[f][x[f,b]][d] * scale[f]
// One thread per output float4. 8 consecutive threads share one (b,f) row:
// gather = 8 consecutive float4 from a single 128B line; stores are linear.
__global__ void __launch_bounds__(256) gather_scale_kernel(
    const int* __restrict__ x,
    const float* __restrict__ tables,
    float* __restrict__ out) {
    const int total = B * F * (D / 4);  // 3,407,872 float4s
    int i = blockIdx.x * blockDim.x + threadIdx.x;
    if (i >= total) return;

    int r  = i >> 3;       // row index = b*F + f
    int d4 = i & 7;        // float4 within the 32-elem row
    int f  = r % F;
    int b  = r / F;

    int idx = __ldg(&x[f * B + b]);
    const float4* src = reinterpret_cast<const float4*>(
        tables + (size_t)f * ((size_t)V * D) + (size_t)idx * D);
    float4 v = src[d4];

    float s = g_scale[f];
    v.x *= s; v.y *= s; v.z *= s; v.w *= s;

    reinterpret_cast<float4*>(out)[i] = v;
}

extern "C" void kernel_launch(void* const* d_in, const int* in_sizes, int n_in,
                              void* d_out, int out_size) {
    const int*   x      = (const int*)d_in[0];
    const float* tables = (const float*)d_in[1];
    const float* w1     = (const float*)d_in[2];
    const float* w2     = (const float*)d_in[3];
    float*       out    = (float*)d_out;

    se_gate_kernel<<<1, 32>>>(x, tables, w1, w2);

    const int total = B * F * (D / 4);
    const int threads = 256;
    const int blocks = (total + threads - 1) / threads;
    gather_scale_kernel<<<blocks, threads>>>(x, tables, out);
}

// round 3
// speedup vs baseline: 1.4951x; 1.4951x over previous
#include <cuda_runtime.h>
#include <cuda_bf16.h>

// Problem constants
#define F 26
#define B 16384
#define V 100000
#define D 32
#define H 13

#define TPB   256
#define ITEMS 16
// total float4s = B*F*(D/4) = 3,407,872 = 832 blocks * 256 threads * 16 items
#define GRID  832

// Fused kernel:
//   prologue (warp 0): scale[f] = sigmoid(w2 @ relu(w1 @ mean_d(emb[f, x[f,B-1], :])))
//     (reference uses ONLY the last batch row for the gate: scale = gate[-1])
//   main: out[b, f*D+d] = tables[f][x[f,b]][d] * scale[f]
// One thread per 16 output float4s; 8 consecutive threads share one (b,f) row so
// each gather reads 8 consecutive float4s of one 128B line; stores are linear.
__global__ void __launch_bounds__(TPB) fused_gather_se_kernel(
    const int* __restrict__ x,
    const float* __restrict__ tables,
    const float* __restrict__ w1,
    const float* __restrict__ w2,
    float* __restrict__ out) {

    __shared__ float s_sein[F];
    __shared__ float s_h[H];
    __shared__ float s_scale[F];

    const int t = threadIdx.x;

    // ---- SE-gate prologue: warp 0 only, redundant per block (L2-hot) ----
    if (t < 32) {
        if (t < F) {
            int idx = __ldg(&x[t * B + (B - 1)]);
            const float4* row = reinterpret_cast<const float4*>(
                tables + (size_t)t * ((size_t)V * D) + (size_t)idx * D);
            float s = 0.f;
            #pragma unroll
            for (int i = 0; i < D / 4; i++) {
                float4 v = __ldg(&row[i]);
                s += (v.x + v.y) + (v.z + v.w);
            }
            s_sein[t] = s * (1.0f / (float)D);
        }
        __syncwarp();
        if (t < H) {
            float acc = 0.f;
            #pragma unroll
            for (int f = 0; f < F; f++) acc += w1[t * F + f] * s_sein[f];
            s_h[t] = fmaxf(acc, 0.f);
        }
        __syncwarp();
        if (t < F) {
            float acc = 0.f;
            #pragma unroll
            for (int j = 0; j < H; j++) acc += w2[t * H + j] * s_h[j];
            s_scale[t] = 1.0f / (1.0f + __expf(-acc));
        }
    }
    __syncthreads();

    // ---- main gather-scale-store, 16 float4s per thread ----
    const int base = blockIdx.x * (TPB * ITEMS) + t;

    // Batch all 16 index loads up front (x[] is 1.7MB -> L2-resident after wave 1)
    int idxs[ITEMS];
    int fs[ITEMS];
    int d4s[ITEMS];
    #pragma unroll
    for (int i = 0; i < ITEMS; i++) {
        int item = base + i * TPB;
        int r  = item >> 3;
        d4s[i] = item & 7;
        int f  = r % F;
        int b  = r / F;
        fs[i]  = f;
        idxs[i] = __ldg(&x[f * B + b]);
    }

    // Gather + scale + store in groups of 4 (MLP=4 in-flight gathers + linear STG)
    #pragma unroll
    for (int g = 0; g < ITEMS / 4; g++) {
        float4 v[4];
        float  sc[4];
        #pragma unroll
        for (int j = 0; j < 4; j++) {
            int i = g * 4 + j;
            const float4* src = reinterpret_cast<const float4*>(
                tables + (size_t)fs[i] * ((size_t)V * D) + (size_t)idxs[i] * D);
            v[j] = __ldg(&src[d4s[i]]);
            sc[j] = s_scale[fs[i]];
        }
        #pragma unroll
        for (int j = 0; j < 4; j++) {
            int i = g * 4 + j;
            v[j].x *= sc[j]; v[j].y *= sc[j]; v[j].z *= sc[j]; v[j].w *= sc[j];
            reinterpret_cast<float4*>(out)[base + i * TPB] = v[j];
        }
    }
}

extern "C" void kernel_launch(void* const* d_in, const int* in_sizes, int n_in,
                              void* d_out, int out_size) {
    const int*   x      = (const int*)d_in[0];
    const float* tables = (const float*)d_in[1];
    const float* w1     = (const float*)d_in[2];
    const float* w2     = (const float*)d_in[3];
    float*       out    = (float*)d_out;

    fused_gather_se_kernel<<<GRID, TPB>>>(x, tables, w1, w2, out);
}

// round 5
// speedup vs baseline: 1.7208x; 1.1509x over previous
#include <cuda_runtime.h>
#include <cuda_bf16.h>

// Problem constants
#define F 26
#define B 16384
#define V 100000
#define D 32
#define H 13

#define TPB   256
#define ITEMS 8
// total float4s = B*F*(D/4) = 3,407,872 = 1664 blocks * 256 threads * 8 items
#define GRID  1664

// Fused kernel:
//   prologue (warp 0): scale[f] = sigmoid(w2 @ relu(w1 @ mean_d(emb[f, x[f,B-1], :])))
//     (reference uses ONLY the last batch row for the gate: scale = gate[-1])
//   main: out[b, f*D+d] = tables[f][x[f,b]][d] * scale[f]
// One thread per 8 output float4s, item stride = TPB. Since TPB % 8 == 0, the
// float4-within-row offset (d4) is constant per thread. 8 consecutive threads
// share one (b,f) row -> each gather LDG.128 touches 4 lines/warp; stores linear.
__global__ void __launch_bounds__(TPB) fused_gather_se_kernel(
    const int* __restrict__ x,
    const float* __restrict__ tables,
    const float* __restrict__ w1,
    const float* __restrict__ w2,
    float* __restrict__ out) {

    __shared__ float s_sein[F];
    __shared__ float s_h[H];
    __shared__ float s_scale[F];

    const int t = threadIdx.x;

    // ---- SE-gate prologue: warp 0 only, redundant per block (L2-hot) ----
    if (t < 32) {
        if (t < F) {
            int idx = __ldg(&x[t * B + (B - 1)]);
            const float4* row = reinterpret_cast<const float4*>(
                tables + (size_t)t * ((size_t)V * D) + (size_t)idx * D);
            float s = 0.f;
            #pragma unroll
            for (int i = 0; i < D / 4; i++) {
                float4 v = __ldg(&row[i]);
                s += (v.x + v.y) + (v.z + v.w);
            }
            s_sein[t] = s * (1.0f / (float)D);
        }
        __syncwarp();
        if (t < H) {
            float acc = 0.f;
            #pragma unroll
            for (int f = 0; f < F; f++) acc += w1[t * F + f] * s_sein[f];
            s_h[t] = fmaxf(acc, 0.f);
        }
        __syncwarp();
        if (t < F) {
            float acc = 0.f;
            #pragma unroll
            for (int j = 0; j < H; j++) acc += w2[t * H + j] * s_h[j];
            s_scale[t] = 1.0f / (1.0f + __expf(-acc));
        }
    }
    __syncthreads();

    // ---- main gather-scale-store, 8 float4s per thread ----
    const int base = blockIdx.x * (TPB * ITEMS) + t;
    const int d4   = base & 7;          // constant across items (TPB % 8 == 0)
    const int r0   = base >> 3;         // row index of item 0; stride 32 rows/item

    // Batch the 8 index loads + src pointers + scales up front (x[] L2-resident)
    const float4* srcs[ITEMS];
    float sc[ITEMS];
    #pragma unroll
    for (int i = 0; i < ITEMS; i++) {
        int r = r0 + i * (TPB / 8);
        int f = r % F;
        int b = r / F;
        sc[i] = s_scale[f];
        int idx = __ldg(&x[f * B + b]);
        srcs[i] = reinterpret_cast<const float4*>(
            tables + (size_t)f * ((size_t)V * D) + (size_t)idx * D) + d4;
    }

    // Gather + scale + streaming store in groups of 4 (MLP>=4 in-flight gathers)
    #pragma unroll
    for (int g = 0; g < ITEMS / 4; g++) {
        float4 v[4];
        #pragma unroll
        for (int j = 0; j < 4; j++) {
            v[j] = __ldg(srcs[g * 4 + j]);
        }
        #pragma unroll
        for (int j = 0; j < 4; j++) {
            int i = g * 4 + j;
            v[j].x *= sc[i]; v[j].y *= sc[i]; v[j].z *= sc[i]; v[j].w *= sc[i];
            // streaming store: output is never re-read; keep table rows in L2
            __stcs(&reinterpret_cast<float4*>(out)[base + i * TPB], v[j]);
        }
    }
}

extern "C" void kernel_launch(void* const* d_in, const int* in_sizes, int n_in,
                              void* d_out, int out_size) {
    const int*   x      = (const int*)d_in[0];
    const float* tables = (const float*)d_in[1];
    const float* w1     = (const float*)d_in[2];
    const float* w2     = (const float*)d_in[3];
    float*       out    = (float*)d_out;

    fused_gather_se_kernel<<<GRID, TPB>>>(x, tables, w1, w2, out);
}